// round 16
// baseline (speedup 1.0000x reference)
#include <cuda_runtime.h>

// ---------------------------------------------------------------------------
// twist_66322884985439: per-row SE(3) joint update.
// Inputs : d_in[0] = T [N,4,4] f32, d_in[1] = q [N,2] f32,
//          d_in[2] = revolute [6] f32, d_in[3] = prismatic [6] f32
// Output : concat( revoluteTwist [N,6], prismaticTwist [N,6], out [N,16] )
//
// FINAL: BLK=64, direct strided streaming loads (__ldcs), MUFU
// transcendentals, smem-staged fully-coalesced streaming flushes (__stcs),
// one block barrier. T-region flush issued first (largest burst earliest).
// 54.4us kernel / ~58us wall, DRAM 72%, 56 regs, rel_err 1.9e-7.
//
// Search history (all axes measured and closed):
//  - input staging (block/warp/cp.async): lost to direct LDGs (R3/R7/R8)
//  - warp-scoped epilogue: lost (R5); block-aligned flush bursts win
//  - occupancy forcing (48 regs): lost (R6); natural 56 regs optimal
//  - 2 rows/thread MLP: lost (R9) to occupancy cost
//  - full-tile despecialization / STG.128 twists: lost (R11/R12)
//  - cache policy .cs on streams: WIN (R10)
//  - BLK 256 -> 128 -> 64: WIN (R4, R14; R14 confirmed in R15)
// ---------------------------------------------------------------------------

__device__ __forceinline__ void srodrigues_one(
    const float w[3], const float v[3], float q,
    float R1[3][3], float p1[3])
{
    float th2 = w[0]*w[0] + w[1]*w[1] + w[2]*w[2];
    float th  = sqrtf(th2);
    float inv = __fdividef(1.0f, fmaxf(th, 1e-12f));
    float wn[3] = { w[0]*inv, w[1]*inv, w[2]*inv };
    float vn[3] = { v[0]*inv, v[1]*inv, v[2]*inv };
    float phi = q * th;
    float s, cph;
    __sincosf(phi, &s, &cph);
    float c  = 1.0f - cph;
    float ps = phi - s;

    float W[3][3]  = { {0.f,   -wn[2],  wn[1]},
                       {wn[2],  0.f,   -wn[0]},
                       {-wn[1], wn[0],  0.f } };

    bool rot = (th > 1e-9f);

#pragma unroll
    for (int a = 0; a < 3; a++) {
        float pacc = 0.0f;
#pragma unroll
        for (int b = 0; b < 3; b++) {
            float I  = (a == b) ? 1.0f : 0.0f;
            float W2 = wn[a]*wn[b] - I;          // W^2 = wn wn^T - I (unit wn)
            float Rv = I     + s*W[a][b] + c *W2;
            float Gv = phi*I + c*W[a][b] + ps*W2;
            R1[a][b] = rot ? Rv : I;
            pacc = fmaf(Gv, vn[b], pacc);
        }
        p1[a] = rot ? pacc : q * v[a];
    }
}

__device__ __forceinline__ void body_twist_one(
    const float R[3][3], const float p[3],
    const float w[3], const float v[3],
    float tw[6])
{
    float t0 = v[0] - (p[1]*w[2] - p[2]*w[1]);
    float t1 = v[1] - (p[2]*w[0] - p[0]*w[2]);
    float t2 = v[2] - (p[0]*w[1] - p[1]*w[0]);
#pragma unroll
    for (int j = 0; j < 3; j++) {
        tw[j]     = R[0][j]*w[0] + R[1][j]*w[1] + R[2][j]*w[2];   // R^T w
        tw[3 + j] = R[0][j]*t0   + R[1][j]*t1   + R[2][j]*t2;     // R^T t
    }
}

__device__ __forceinline__ void compose(
    const float Ra[3][3], const float pa[3],
    const float Rb[3][3], const float pb[3],
    float Rc[3][3], float pc[3])
{
#pragma unroll
    for (int a = 0; a < 3; a++) {
#pragma unroll
        for (int b = 0; b < 3; b++) {
            Rc[a][b] = fmaf(Ra[a][0], Rb[0][b],
                       fmaf(Ra[a][1], Rb[1][b],
                            Ra[a][2] * Rb[2][b]));
        }
        pc[a] = fmaf(Ra[a][0], pb[0],
                fmaf(Ra[a][1], pb[1],
                fmaf(Ra[a][2], pb[2], pa[a])));
    }
}

#define BLK 64

__global__ void __launch_bounds__(BLK)
twist_kernel(const float* __restrict__ Tin,
             const float* __restrict__ qin,
             const float* __restrict__ rev,
             const float* __restrict__ pri,
             float* __restrict__ out,
             int n)
{
    __shared__ float2 s_tw1[BLK * 3];
    __shared__ float2 s_tw2[BLK * 3];
    __shared__ float4 s_T [BLK * 5];   // stride-5 float4 rows: STS/LDS friendly

    const int t = threadIdx.x;
    const size_t base = (size_t)blockIdx.x * BLK;
    const int i = (int)base + t;
    const int rows = min(BLK, n - (int)base);

    if (i < n) {
        // direct strided loads, streaming (evict-first) — zero reuse
        const float4* tp = reinterpret_cast<const float4*>(Tin) + (size_t)i * 4;
        float4 a0 = __ldcs(tp + 0), a1 = __ldcs(tp + 1), a2 = __ldcs(tp + 2);
        float R[3][3] = { {a0.x, a0.y, a0.z},
                          {a1.x, a1.y, a1.z},
                          {a2.x, a2.y, a2.z} };
        float p[3] = { a0.w, a1.w, a2.w };

        float2 q = __ldcs(reinterpret_cast<const float2*>(qin) + i);

        float4 r03 = __ldg(reinterpret_cast<const float4*>(rev));
        float2 r45 = __ldg(reinterpret_cast<const float2*>(rev + 4));
        float4 p03 = __ldg(reinterpret_cast<const float4*>(pri));
        float2 p45 = __ldg(reinterpret_cast<const float2*>(pri + 4));
        float wr[3] = { r03.x, r03.y, r03.z };
        float vr[3] = { r03.w, r45.x, r45.y };
        float wp[3] = { p03.x, p03.y, p03.z };
        float vp[3] = { p03.w, p45.x, p45.y };

        // revolute twist on T
        float tw1[6];
        body_twist_one(R, p, wr, vr, tw1);

        // T = T * exp(revolute * q0)
        float R1[3][3], p1[3];
        srodrigues_one(wr, vr, q.x, R1, p1);
        float Rn[3][3], pn[3];
        compose(R, p, R1, p1, Rn, pn);

        // prismatic twist on updated T
        float tw2[6];
        body_twist_one(Rn, pn, wp, vp, tw2);

        // T = T * exp(prismatic * q1)
        float R2[3][3], p2[3];
        srodrigues_one(wp, vp, q.y, R2, p2);
        float Rf[3][3], pf[3];
        compose(Rn, pn, R2, p2, Rf, pf);

        // --- stage everything into smem (vectorized) ---
        s_tw1[t*3 + 0] = make_float2(tw1[0], tw1[1]);
        s_tw1[t*3 + 1] = make_float2(tw1[2], tw1[3]);
        s_tw1[t*3 + 2] = make_float2(tw1[4], tw1[5]);
        s_tw2[t*3 + 0] = make_float2(tw2[0], tw2[1]);
        s_tw2[t*3 + 1] = make_float2(tw2[2], tw2[3]);
        s_tw2[t*3 + 2] = make_float2(tw2[4], tw2[5]);
        s_T[t*5 + 0] = make_float4(Rf[0][0], Rf[0][1], Rf[0][2], pf[0]);
        s_T[t*5 + 1] = make_float4(Rf[1][0], Rf[1][1], Rf[1][2], pf[1]);
        s_T[t*5 + 2] = make_float4(Rf[2][0], Rf[2][1], Rf[2][2], pf[2]);
        s_T[t*5 + 3] = make_float4(0.0f, 0.0f, 0.0f, 1.0f);
    }

    __syncthreads();

    // --- coalesced streaming flushes: largest region (T, 16/28 bytes) first ---
    const size_t N = (size_t)n;
    const int nf4 = rows * 4;

    {   // out 4x4 at floats [12N, 28N): float4 view
        float4* dst = reinterpret_cast<float4*>(out + 12 * N) + base * 4;
#pragma unroll
        for (int k = 0; k < 4; k++) {
            int m = k * BLK + t;
            if (m < nf4) __stcs(dst + m, s_T[(m >> 2) * 5 + (m & 3)]);
        }
    }
    {   // revoluteTwist at floats [0, 6N): float2 view
        float2* dst = reinterpret_cast<float2*>(out) + base * 3;
        const int lim = rows * 3;
#pragma unroll
        for (int k = 0; k < 3; k++) {
            int m = k * BLK + t;
            if (m < lim) __stcs(dst + m, s_tw1[m]);
        }
    }
    {   // prismaticTwist at floats [6N, 12N)
        float2* dst = reinterpret_cast<float2*>(out) + N * 3 + base * 3;
        const int lim = rows * 3;
#pragma unroll
        for (int k = 0; k < 3; k++) {
            int m = k * BLK + t;
            if (m < lim) __stcs(dst + m, s_tw2[m]);
        }
    }
}

extern "C" void kernel_launch(void* const* d_in, const int* in_sizes, int n_in,
                              void* d_out, int out_size)
{
    const float* Tin = (const float*)d_in[0];
    const float* qin = (const float*)d_in[1];
    const float* rev = (const float*)d_in[2];
    const float* pri = (const float*)d_in[3];
    float* out = (float*)d_out;

    int n = in_sizes[0] / 16;   // [N,4,4]
    int blocks = (n + BLK - 1) / BLK;
    twist_kernel<<<blocks, BLK>>>(Tin, qin, rev, pri, out, n);
}

// round 17
// speedup vs baseline: 1.2479x; 1.2479x over previous
#include <cuda_runtime.h>

// ---------------------------------------------------------------------------
// twist_66322884985439: per-row SE(3) joint update.
// Inputs : d_in[0] = T [N,4,4] f32, d_in[1] = q [N,2] f32,
//          d_in[2] = revolute [6] f32, d_in[3] = prismatic [6] f32
// Output : concat( revoluteTwist [N,6], prismaticTwist [N,6], out [N,16] )
//
// FINAL (R14 configuration, confirmed twice at ~54.4us ncu / ~58us wall):
// BLK=64, direct strided streaming loads (__ldcs), MUFU transcendentals,
// smem-staged fully-coalesced streaming flushes (__stcs) in twists-then-T
// order (ORDER MATTERS — R16 showed T-first collapses epilogue scheduling),
// one block barrier. DRAM 72%, 56 regs, rel_err 1.9e-7.
//
// Search history (all axes measured and closed):
//  - input staging (block/warp/cp.async): lost to direct LDGs (R3/R7/R8)
//  - warp-scoped epilogue: lost (R5); block-aligned flush bursts win
//  - occupancy forcing (48 regs): lost (R6); natural 56 regs optimal
//  - 2 rows/thread MLP: lost (R9) to occupancy cost
//  - full-tile despecialization / STG.128 twists: lost (R11/R12)
//  - cache policy .cs on streams: WIN (R10)
//  - BLK 256 -> 128 -> 64: WIN (R4, R14; confirmed R15)
//  - flush reorder (T first): LOST badly (R16) — keep twists first
// ---------------------------------------------------------------------------

__device__ __forceinline__ void srodrigues_one(
    const float w[3], const float v[3], float q,
    float R1[3][3], float p1[3])
{
    float th2 = w[0]*w[0] + w[1]*w[1] + w[2]*w[2];
    float th  = sqrtf(th2);
    float inv = __fdividef(1.0f, fmaxf(th, 1e-12f));
    float wn[3] = { w[0]*inv, w[1]*inv, w[2]*inv };
    float vn[3] = { v[0]*inv, v[1]*inv, v[2]*inv };
    float phi = q * th;
    float s, cph;
    __sincosf(phi, &s, &cph);
    float c  = 1.0f - cph;
    float ps = phi - s;

    float W[3][3]  = { {0.f,   -wn[2],  wn[1]},
                       {wn[2],  0.f,   -wn[0]},
                       {-wn[1], wn[0],  0.f } };

    bool rot = (th > 1e-9f);

#pragma unroll
    for (int a = 0; a < 3; a++) {
        float pacc = 0.0f;
#pragma unroll
        for (int b = 0; b < 3; b++) {
            float I  = (a == b) ? 1.0f : 0.0f;
            float W2 = wn[a]*wn[b] - I;          // W^2 = wn wn^T - I (unit wn)
            float Rv = I     + s*W[a][b] + c *W2;
            float Gv = phi*I + c*W[a][b] + ps*W2;
            R1[a][b] = rot ? Rv : I;
            pacc = fmaf(Gv, vn[b], pacc);
        }
        p1[a] = rot ? pacc : q * v[a];
    }
}

__device__ __forceinline__ void body_twist_one(
    const float R[3][3], const float p[3],
    const float w[3], const float v[3],
    float tw[6])
{
    float t0 = v[0] - (p[1]*w[2] - p[2]*w[1]);
    float t1 = v[1] - (p[2]*w[0] - p[0]*w[2]);
    float t2 = v[2] - (p[0]*w[1] - p[1]*w[0]);
#pragma unroll
    for (int j = 0; j < 3; j++) {
        tw[j]     = R[0][j]*w[0] + R[1][j]*w[1] + R[2][j]*w[2];   // R^T w
        tw[3 + j] = R[0][j]*t0   + R[1][j]*t1   + R[2][j]*t2;     // R^T t
    }
}

__device__ __forceinline__ void compose(
    const float Ra[3][3], const float pa[3],
    const float Rb[3][3], const float pb[3],
    float Rc[3][3], float pc[3])
{
#pragma unroll
    for (int a = 0; a < 3; a++) {
#pragma unroll
        for (int b = 0; b < 3; b++) {
            Rc[a][b] = fmaf(Ra[a][0], Rb[0][b],
                       fmaf(Ra[a][1], Rb[1][b],
                            Ra[a][2] * Rb[2][b]));
        }
        pc[a] = fmaf(Ra[a][0], pb[0],
                fmaf(Ra[a][1], pb[1],
                fmaf(Ra[a][2], pb[2], pa[a])));
    }
}

#define BLK 64

__global__ void __launch_bounds__(BLK)
twist_kernel(const float* __restrict__ Tin,
             const float* __restrict__ qin,
             const float* __restrict__ rev,
             const float* __restrict__ pri,
             float* __restrict__ out,
             int n)
{
    __shared__ float2 s_tw1[BLK * 3];
    __shared__ float2 s_tw2[BLK * 3];
    __shared__ float4 s_T [BLK * 5];   // stride-5 float4 rows: STS/LDS friendly

    const int t = threadIdx.x;
    const size_t base = (size_t)blockIdx.x * BLK;
    const int i = (int)base + t;
    const int rows = min(BLK, n - (int)base);

    if (i < n) {
        // direct strided loads, streaming (evict-first) — zero reuse
        const float4* tp = reinterpret_cast<const float4*>(Tin) + (size_t)i * 4;
        float4 a0 = __ldcs(tp + 0), a1 = __ldcs(tp + 1), a2 = __ldcs(tp + 2);
        float R[3][3] = { {a0.x, a0.y, a0.z},
                          {a1.x, a1.y, a1.z},
                          {a2.x, a2.y, a2.z} };
        float p[3] = { a0.w, a1.w, a2.w };

        float2 q = __ldcs(reinterpret_cast<const float2*>(qin) + i);

        float4 r03 = __ldg(reinterpret_cast<const float4*>(rev));
        float2 r45 = __ldg(reinterpret_cast<const float2*>(rev + 4));
        float4 p03 = __ldg(reinterpret_cast<const float4*>(pri));
        float2 p45 = __ldg(reinterpret_cast<const float2*>(pri + 4));
        float wr[3] = { r03.x, r03.y, r03.z };
        float vr[3] = { r03.w, r45.x, r45.y };
        float wp[3] = { p03.x, p03.y, p03.z };
        float vp[3] = { p03.w, p45.x, p45.y };

        // revolute twist on T
        float tw1[6];
        body_twist_one(R, p, wr, vr, tw1);

        // T = T * exp(revolute * q0)
        float R1[3][3], p1[3];
        srodrigues_one(wr, vr, q.x, R1, p1);
        float Rn[3][3], pn[3];
        compose(R, p, R1, p1, Rn, pn);

        // prismatic twist on updated T
        float tw2[6];
        body_twist_one(Rn, pn, wp, vp, tw2);

        // T = T * exp(prismatic * q1)
        float R2[3][3], p2[3];
        srodrigues_one(wp, vp, q.y, R2, p2);
        float Rf[3][3], pf[3];
        compose(Rn, pn, R2, p2, Rf, pf);

        // --- stage everything into smem (vectorized) ---
        s_tw1[t*3 + 0] = make_float2(tw1[0], tw1[1]);
        s_tw1[t*3 + 1] = make_float2(tw1[2], tw1[3]);
        s_tw1[t*3 + 2] = make_float2(tw1[4], tw1[5]);
        s_tw2[t*3 + 0] = make_float2(tw2[0], tw2[1]);
        s_tw2[t*3 + 1] = make_float2(tw2[2], tw2[3]);
        s_tw2[t*3 + 2] = make_float2(tw2[4], tw2[5]);
        s_T[t*5 + 0] = make_float4(Rf[0][0], Rf[0][1], Rf[0][2], pf[0]);
        s_T[t*5 + 1] = make_float4(Rf[1][0], Rf[1][1], Rf[1][2], pf[1]);
        s_T[t*5 + 2] = make_float4(Rf[2][0], Rf[2][1], Rf[2][2], pf[2]);
        s_T[t*5 + 3] = make_float4(0.0f, 0.0f, 0.0f, 1.0f);
    }

    __syncthreads();

    // --- coalesced streaming flushes (twists first, then T — order matters) ---
    const size_t N = (size_t)n;
    const int nf4 = rows * 4;

    {   // revoluteTwist at floats [0, 6N): float2 view
        float2* dst = reinterpret_cast<float2*>(out) + base * 3;
        const int lim = rows * 3;
#pragma unroll
        for (int k = 0; k < 3; k++) {
            int m = k * BLK + t;
            if (m < lim) __stcs(dst + m, s_tw1[m]);
        }
    }
    {   // prismaticTwist at floats [6N, 12N)
        float2* dst = reinterpret_cast<float2*>(out) + N * 3 + base * 3;
        const int lim = rows * 3;
#pragma unroll
        for (int k = 0; k < 3; k++) {
            int m = k * BLK + t;
            if (m < lim) __stcs(dst + m, s_tw2[m]);
        }
    }
    {   // out 4x4 at floats [12N, 28N): float4 view
        float4* dst = reinterpret_cast<float4*>(out + 12 * N) + base * 4;
#pragma unroll
        for (int k = 0; k < 4; k++) {
            int m = k * BLK + t;
            if (m < nf4) __stcs(dst + m, s_T[(m >> 2) * 5 + (m & 3)]);
        }
    }
}

extern "C" void kernel_launch(void* const* d_in, const int* in_sizes, int n_in,
                              void* d_out, int out_size)
{
    const float* Tin = (const float*)d_in[0];
    const float* qin = (const float*)d_in[1];
    const float* rev = (const float*)d_in[2];
    const float* pri = (const float*)d_in[3];
    float* out = (float*)d_out;

    int n = in_sizes[0] / 16;   // [N,4,4]
    int blocks = (n + BLK - 1) / BLK;
    twist_kernel<<<blocks, BLK>>>(Tin, qin, rev, pri, out, n);
}